// round 4
// baseline (speedup 1.0000x reference)
#include <cuda_runtime.h>
#include <cuda_bf16.h>
#include <math.h>

// Problem constants
#define B 8
#define L 1500
#define D 1024
#define H 8
#define HD 128
#define S 300
#define SCALE 0.08838834764831845f   // 1/sqrt(128)
#define EPS 1e-5f

// ---------------- scratch (device globals; no allocation allowed) -------------
__device__ float g_hn[B * L * D];            // 49.2 MB  normalized hidden
__device__ float g_scores[B * H * L];        // scores per (b,h,t)
__device__ float g_w[B * H * L];             // softmax weights per token
__device__ float g_qk[H * D];                // folded q @ Wk
__device__ float g_pooledH[B * S * H * D];   // 78.6 MB  per-head pooled hn
__device__ float g_pooled[B * S * D];        // 9.8 MB
__device__ int   g_seg_start[B * S];
__device__ int   g_seg_cnt[B * S];

// ---------------- helpers -----------------------------------------------------
__device__ __forceinline__ float warp_sum(float v) {
#pragma unroll
    for (int o = 16; o > 0; o >>= 1) v += __shfl_xor_sync(0xffffffffu, v, o);
    return v;
}
__device__ __forceinline__ float warp_max(float v) {
#pragma unroll
    for (int o = 16; o > 0; o >>= 1) v = fmaxf(v, __shfl_xor_sync(0xffffffffu, v, o));
    return v;
}

// ---------------- 1) segment ranges -------------------------------------------
// seg_id[t] = cumsum(boundaries) - boundaries ; contiguous ranges.
__global__ void seg_kernel(const float* __restrict__ boundaries,
                           const float* __restrict__ lengths) {
    __shared__ float sb[L];
    __shared__ int scnt[S];
    __shared__ int sstart[S];
    int b = blockIdx.x;
    for (int i = threadIdx.x; i < L; i += blockDim.x) sb[i] = boundaries[b * L + i];
    for (int i = threadIdx.x; i < S; i += blockDim.x) { scnt[i] = 0; sstart[i] = 0; }
    __syncthreads();
    if (threadIdx.x == 0) {
        int alen = (int)(lengths[b] * (float)L);   // truncation, matches astype(int32)
        int cum = 0;
        for (int t = 0; t < L; t++) {
            int bd = sb[t] > 0.5f ? 1 : 0;
            cum += bd;
            int sid = cum - bd;
            if (t < alen && sid < S) {
                if (scnt[sid] == 0) sstart[sid] = t;
                scnt[sid]++;
            }
        }
    }
    __syncthreads();
    for (int i = threadIdx.x; i < S; i += blockDim.x) {
        g_seg_cnt[b * S + i]   = scnt[i];
        g_seg_start[b * S + i] = sstart[i];
    }
}

// ---------------- 2) qk[h,j] = sum_hd q[h*HD+hd] * Wk[h*HD+hd, j] --------------
__global__ void qk_kernel(const float* __restrict__ q, const float* __restrict__ Wk) {
    int idx = blockIdx.x * blockDim.x + threadIdx.x;   // h*D + j
    if (idx >= H * D) return;
    int h = idx >> 10, j = idx & (D - 1);
    float acc = 0.f;
#pragma unroll 8
    for (int hd = 0; hd < HD; hd++)
        acc += q[h * HD + hd] * Wk[(h * HD + hd) * D + j];
    g_qk[idx] = acc;
}

// ---------------- 3) LayerNorm + scores fused (block per token) ----------------
__global__ void __launch_bounds__(256) ln_scores_kernel(
    const float* __restrict__ hidden, const float* __restrict__ gamma,
    const float* __restrict__ beta) {
    int tok = blockIdx.x;            // b*L + t
    int b = tok / L, t = tok - b * L;
    int tid = threadIdx.x;           // 256, each owns a float4 (D=1024)
    int lane = tid & 31, wid = tid >> 5;

    float4 x = ((const float4*)(hidden + (size_t)tok * D))[tid];
    float s  = x.x + x.y + x.z + x.w;
    float ss = x.x * x.x + x.y * x.y + x.z * x.z + x.w * x.w;

    __shared__ float sred[2][8];
    float ws  = warp_sum(s);
    float wss = warp_sum(ss);
    if (lane == 0) { sred[0][wid] = ws; sred[1][wid] = wss; }
    __syncthreads();
    __shared__ float stats[2];
    if (tid == 0) {
        float a = 0.f, b2 = 0.f;
#pragma unroll
        for (int i = 0; i < 8; i++) { a += sred[0][i]; b2 += sred[1][i]; }
        float mean = a * (1.f / (float)D);
        float var  = b2 * (1.f / (float)D) - mean * mean;
        stats[0] = mean;
        stats[1] = rsqrtf(var + EPS);
    }
    __syncthreads();
    float mean = stats[0], rstd = stats[1];

    float4 g  = ((const float4*)gamma)[tid];
    float4 be = ((const float4*)beta)[tid];
    float4 hv;
    hv.x = (x.x - mean) * rstd * g.x + be.x;
    hv.y = (x.y - mean) * rstd * g.y + be.y;
    hv.z = (x.z - mean) * rstd * g.z + be.z;
    hv.w = (x.w - mean) * rstd * g.w + be.w;
    ((float4*)(g_hn + (size_t)tok * D))[tid] = hv;

    // per-head partial dot products with folded qk
    float p[H];
#pragma unroll
    for (int h = 0; h < H; h++) {
        float4 qv = ((const float4*)g_qk)[h * (D / 4) + tid];
        p[h] = hv.x * qv.x + hv.y * qv.y + hv.z * qv.z + hv.w * qv.w;
    }
    __shared__ float pred[H][8];
#pragma unroll
    for (int h = 0; h < H; h++) {
        float ph = warp_sum(p[h]);
        if (lane == 0) pred[h][wid] = ph;
    }
    __syncthreads();
    if (tid < H) {
        float v = 0.f;
#pragma unroll
        for (int w = 0; w < 8; w++) v += pred[tid][w];
        g_scores[((size_t)b * H + tid) * L + t] = v * SCALE;
    }
}

// ---------------- 4) segment softmax (block per (b,s); warp per head) ----------
__global__ void softmax_kernel() {
    int bs = blockIdx.x;             // b*S + s
    int b = bs / S;
    int st = g_seg_start[bs], cnt = g_seg_cnt[bs];
    if (cnt == 0) return;
    int lane = threadIdx.x & 31, h = threadIdx.x >> 5;   // 8 warps = 8 heads
    const float* srow = g_scores + ((size_t)b * H + h) * L + st;
    float mx = -1e30f;
    for (int i = lane; i < cnt; i += 32) mx = fmaxf(mx, srow[i]);
    mx = warp_max(mx);
    float sum = 0.f;
    for (int i = lane; i < cnt; i += 32) sum += expf(srow[i] - mx);
    sum = warp_sum(sum);
    float inv = 1.f / sum;
    float* wrow = g_w + ((size_t)b * H + h) * L + st;
    for (int i = lane; i < cnt; i += 32) wrow[i] = expf(srow[i] - mx) * inv;
}

// ---------------- 5) sparse pooling: pooledH[bs,h,:] = sum_t w * hn ------------
__global__ void __launch_bounds__(256) pool_kernel() {
    int bs = blockIdx.x;             // b*S + s
    int b = bs / S;
    int tid = threadIdx.x;           // 256 threads, float4 over D
    int st = g_seg_start[bs], cnt = g_seg_cnt[bs];
    float4 acc[H];
#pragma unroll
    for (int h = 0; h < H; h++) acc[h] = make_float4(0.f, 0.f, 0.f, 0.f);
    for (int i = 0; i < cnt; i++) {
        int t = st + i;
        float4 x = ((const float4*)(g_hn + ((size_t)(b * L + t)) * D))[tid];
        float wh[H];
#pragma unroll
        for (int h = 0; h < H; h++) wh[h] = g_w[((size_t)b * H + h) * L + t];
#pragma unroll
        for (int h = 0; h < H; h++) {
            acc[h].x += wh[h] * x.x;
            acc[h].y += wh[h] * x.y;
            acc[h].z += wh[h] * x.z;
            acc[h].w += wh[h] * x.w;
        }
    }
#pragma unroll
    for (int h = 0; h < H; h++)
        ((float4*)(g_pooledH + ((size_t)bs * H + h) * D))[tid] = acc[h];
}

// ---------------- 6/7) generic SGEMM: C[m,n] = sum_k A[m,k] * W[n,k] -----------
// 128x128 block tile, 8x8 microtile, BK=8, 256 threads. K fixed to 1024.
__global__ void __launch_bounds__(256) sgemm_kernel(
    const float* __restrict__ A, int lda,
    const float* __restrict__ W,
    float* __restrict__ C, int ldc,
    int M, int N, int bsA, int bsW, int bsC) {
    A += (size_t)blockIdx.z * bsA;
    W += (size_t)blockIdx.z * bsW;
    C += (size_t)blockIdx.z * bsC;
    const int K = 1024;
    __shared__ float As[8][128];
    __shared__ float Ws[8][128];
    int tid  = threadIdx.x;
    int lrow = tid >> 1;
    int lcol = (tid & 1) << 2;
    int tx = tid & 15;   // n
    int ty = tid >> 4;   // m
    int m0 = blockIdx.x * 128;
    int n0 = blockIdx.y * 128;

    float acc[8][8];
#pragma unroll
    for (int i = 0; i < 8; i++)
#pragma unroll
        for (int j = 0; j < 8; j++) acc[i][j] = 0.f;

    int arow = m0 + lrow;
    bool avalid = arow < M;
    const float* Aptr = A + (size_t)arow * lda + lcol;
    const float* Wptr = W + (size_t)(n0 + lrow) * K + lcol;

    for (int k0 = 0; k0 < K; k0 += 8) {
        float4 av = avalid ? *(const float4*)(Aptr + k0) : make_float4(0.f, 0.f, 0.f, 0.f);
        float4 wv = *(const float4*)(Wptr + k0);
        As[lcol + 0][lrow] = av.x; As[lcol + 1][lrow] = av.y;
        As[lcol + 2][lrow] = av.z; As[lcol + 3][lrow] = av.w;
        Ws[lcol + 0][lrow] = wv.x; Ws[lcol + 1][lrow] = wv.y;
        Ws[lcol + 2][lrow] = wv.z; Ws[lcol + 3][lrow] = wv.w;
        __syncthreads();
#pragma unroll
        for (int k = 0; k < 8; k++) {
            float a[8], bb[8];
            *(float4*)&a[0]  = *(const float4*)&As[k][ty * 8];
            *(float4*)&a[4]  = *(const float4*)&As[k][ty * 8 + 4];
            *(float4*)&bb[0] = *(const float4*)&Ws[k][tx * 8];
            *(float4*)&bb[4] = *(const float4*)&Ws[k][tx * 8 + 4];
#pragma unroll
            for (int i = 0; i < 8; i++)
#pragma unroll
                for (int j = 0; j < 8; j++) acc[i][j] += a[i] * bb[j];
        }
        __syncthreads();
    }
#pragma unroll
    for (int i = 0; i < 8; i++) {
        int m = m0 + ty * 8 + i;
        if (m < M) {
            float* crow = C + (size_t)m * ldc + n0 + tx * 8;
            ((float4*)crow)[0] = make_float4(acc[i][0], acc[i][1], acc[i][2], acc[i][3]);
            ((float4*)crow)[1] = make_float4(acc[i][4], acc[i][5], acc[i][6], acc[i][7]);
        }
    }
}

// ---------------- launch -------------------------------------------------------
extern "C" void kernel_launch(void* const* d_in, const int* in_sizes, int n_in,
                              void* d_out, int out_size) {
    const float* hidden     = (const float*)d_in[0];
    const float* boundaries = (const float*)d_in[1];
    const float* lengths    = (const float*)d_in[2];
    const float* lquery     = (const float*)d_in[3];
    const float* Wk         = (const float*)d_in[4];
    const float* Wv         = (const float*)d_in[5];
    const float* Wo         = (const float*)d_in[6];
    const float* gamma      = (const float*)d_in[7];
    const float* beta       = (const float*)d_in[8];
    float* out = (float*)d_out;

    float *p_pooledH, *p_pooled;
    cudaGetSymbolAddress((void**)&p_pooledH, g_pooledH);
    cudaGetSymbolAddress((void**)&p_pooled,  g_pooled);

    seg_kernel<<<B, 256>>>(boundaries, lengths);
    qk_kernel<<<(H * D + 255) / 256, 256>>>(lquery, Wk);
    ln_scores_kernel<<<B * L, 256>>>(hidden, gamma, beta);
    softmax_kernel<<<B * S, 256>>>();
    pool_kernel<<<B * S, 256>>>();

    // step 6: pooled[bs, h*128+n] = sum_k pooledH[bs,h,k] * Wv[h*128+n, k]
    {
        dim3 grid((B * S + 127) / 128, 1, H);
        sgemm_kernel<<<grid, 256>>>(p_pooledH, H * D, Wv, p_pooled, D,
                                    B * S, HD, D, HD * D, HD);
    }
    // step 7: out[bs, n] = sum_k pooled[bs,k] * Wo[n,k]
    {
        dim3 grid((B * S + 127) / 128, D / 128, 1);
        sgemm_kernel<<<grid, 256>>>(p_pooled, D, Wo, out, D,
                                    B * S, D, 0, 0, 0);
    }
}

// round 6
// speedup vs baseline: 1.6914x; 1.6914x over previous
#include <cuda_runtime.h>
#include <cuda_bf16.h>
#include <math.h>
#include <stdint.h>

// Problem constants
#define B 8
#define L 1500
#define D 1024
#define H 8
#define HD 128
#define S 300
#define SCALE 0.08838834764831845f   // 1/sqrt(128)
#define EPS 1e-5f

// ---------------- scratch (device globals; no allocation allowed) -------------
__device__ float g_hn[B * L * D];            // 49.2 MB  normalized hidden
__device__ float g_scores[B * H * L];        // scores per (b,h,t)
__device__ float g_w[B * H * L];             // softmax weights per token
__device__ float g_qk[H * D];                // folded q @ Wk
__device__ float g_pooledH[B * S * H * D];   // 78.6 MB  per-head pooled hn
__device__ float g_pooled[B * S * D];        // 9.8 MB
__device__ int   g_seg_start[B * S];
__device__ int   g_seg_cnt[B * S];

// ---------------- warp helpers -------------------------------------------------
__device__ __forceinline__ float warp_sum(float v) {
#pragma unroll
    for (int o = 16; o > 0; o >>= 1) v += __shfl_xor_sync(0xffffffffu, v, o);
    return v;
}
__device__ __forceinline__ float warp_max(float v) {
#pragma unroll
    for (int o = 16; o > 0; o >>= 1) v = fmaxf(v, __shfl_xor_sync(0xffffffffu, v, o));
    return v;
}

// ---------------- 1) segment ranges -------------------------------------------
__global__ void seg_kernel(const float* __restrict__ boundaries,
                           const float* __restrict__ lengths) {
    __shared__ float sb[L];
    __shared__ int scnt[S];
    __shared__ int sstart[S];
    int b = blockIdx.x;
    for (int i = threadIdx.x; i < L; i += blockDim.x) sb[i] = boundaries[b * L + i];
    for (int i = threadIdx.x; i < S; i += blockDim.x) { scnt[i] = 0; sstart[i] = 0; }
    __syncthreads();
    if (threadIdx.x == 0) {
        int alen = (int)(lengths[b] * (float)L);
        int cum = 0;
        for (int t = 0; t < L; t++) {
            int bd = sb[t] > 0.5f ? 1 : 0;
            cum += bd;
            int sid = cum - bd;
            if (t < alen && sid < S) {
                if (scnt[sid] == 0) sstart[sid] = t;
                scnt[sid]++;
            }
        }
    }
    __syncthreads();
    for (int i = threadIdx.x; i < S; i += blockDim.x) {
        g_seg_cnt[b * S + i]   = scnt[i];
        g_seg_start[b * S + i] = sstart[i];
    }
}

// ---------------- 2) qk[h,j] = sum_hd q[h*HD+hd] * Wk[h*HD+hd, j] --------------
__global__ void qk_kernel(const float* __restrict__ q, const float* __restrict__ Wk) {
    int idx = blockIdx.x * blockDim.x + threadIdx.x;   // h*D + j
    if (idx >= H * D) return;
    int h = idx >> 10, j = idx & (D - 1);
    float acc = 0.f;
#pragma unroll 8
    for (int hd = 0; hd < HD; hd++)
        acc += q[h * HD + hd] * Wk[(h * HD + hd) * D + j];
    g_qk[idx] = acc;
}

// ---------------- 3) LayerNorm + scores fused (block per token) ----------------
__global__ void __launch_bounds__(256) ln_scores_kernel(
    const float* __restrict__ hidden, const float* __restrict__ gamma,
    const float* __restrict__ beta) {
    int tok = blockIdx.x;            // b*L + t
    int b = tok / L, t = tok - b * L;
    int tid = threadIdx.x;
    int lane = tid & 31, wid = tid >> 5;

    float4 x = ((const float4*)(hidden + (size_t)tok * D))[tid];
    float s  = x.x + x.y + x.z + x.w;
    float ss = x.x * x.x + x.y * x.y + x.z * x.z + x.w * x.w;

    __shared__ float sred[2][8];
    float ws  = warp_sum(s);
    float wss = warp_sum(ss);
    if (lane == 0) { sred[0][wid] = ws; sred[1][wid] = wss; }
    __syncthreads();
    __shared__ float stats[2];
    if (tid == 0) {
        float a = 0.f, b2 = 0.f;
#pragma unroll
        for (int i = 0; i < 8; i++) { a += sred[0][i]; b2 += sred[1][i]; }
        float mean = a * (1.f / (float)D);
        float var  = b2 * (1.f / (float)D) - mean * mean;
        stats[0] = mean;
        stats[1] = rsqrtf(var + EPS);
    }
    __syncthreads();
    float mean = stats[0], rstd = stats[1];

    float4 g  = ((const float4*)gamma)[tid];
    float4 be = ((const float4*)beta)[tid];
    float4 hv;
    hv.x = (x.x - mean) * rstd * g.x + be.x;
    hv.y = (x.y - mean) * rstd * g.y + be.y;
    hv.z = (x.z - mean) * rstd * g.z + be.z;
    hv.w = (x.w - mean) * rstd * g.w + be.w;
    ((float4*)(g_hn + (size_t)tok * D))[tid] = hv;

    float p[H];
#pragma unroll
    for (int h = 0; h < H; h++) {
        float4 qv = ((const float4*)g_qk)[h * (D / 4) + tid];
        p[h] = hv.x * qv.x + hv.y * qv.y + hv.z * qv.z + hv.w * qv.w;
    }
    __shared__ float pred[H][8];
#pragma unroll
    for (int h = 0; h < H; h++) {
        float ph = warp_sum(p[h]);
        if (lane == 0) pred[h][wid] = ph;
    }
    __syncthreads();
    if (tid < H) {
        float v = 0.f;
#pragma unroll
        for (int w = 0; w < 8; w++) v += pred[tid][w];
        g_scores[((size_t)b * H + tid) * L + t] = v * SCALE;
    }
}

// ---------------- 4) segment softmax (block per (b,s); warp per head) ----------
__global__ void softmax_kernel() {
    int bs = blockIdx.x;
    int b = bs / S;
    int st = g_seg_start[bs], cnt = g_seg_cnt[bs];
    if (cnt == 0) return;
    int lane = threadIdx.x & 31, h = threadIdx.x >> 5;
    const float* srow = g_scores + ((size_t)b * H + h) * L + st;
    float mx = -1e30f;
    for (int i = lane; i < cnt; i += 32) mx = fmaxf(mx, srow[i]);
    mx = warp_max(mx);
    float sum = 0.f;
    for (int i = lane; i < cnt; i += 32) sum += expf(srow[i] - mx);
    sum = warp_sum(sum);
    float inv = 1.f / sum;
    float* wrow = g_w + ((size_t)b * H + h) * L + st;
    for (int i = lane; i < cnt; i += 32) wrow[i] = expf(srow[i] - mx) * inv;
}

// ---------------- 5) sparse pooling: pooledH[bs,h,:] = sum_t w * hn ------------
__global__ void __launch_bounds__(256) pool_kernel() {
    int bs = blockIdx.x;
    int b = bs / S;
    int tid = threadIdx.x;
    int st = g_seg_start[bs], cnt = g_seg_cnt[bs];
    float4 acc[H];
#pragma unroll
    for (int h = 0; h < H; h++) acc[h] = make_float4(0.f, 0.f, 0.f, 0.f);
    for (int i = 0; i < cnt; i++) {
        int t = st + i;
        float4 x = ((const float4*)(g_hn + ((size_t)(b * L + t)) * D))[tid];
        float wh[H];
#pragma unroll
        for (int h = 0; h < H; h++) wh[h] = g_w[((size_t)b * H + h) * L + t];
#pragma unroll
        for (int h = 0; h < H; h++) {
            acc[h].x += wh[h] * x.x;
            acc[h].y += wh[h] * x.y;
            acc[h].z += wh[h] * x.z;
            acc[h].w += wh[h] * x.w;
        }
    }
#pragma unroll
    for (int h = 0; h < H; h++)
        ((float4*)(g_pooledH + ((size_t)bs * H + h) * D))[tid] = acc[h];
}

// ---------------- 6/7) mma.sync bf16 split-precision GEMM ----------------------
// C[m,n] = sum_k A[m,k] * W[n,k], K=1024, fp32 in/out.
// Split in-kernel: x = hi + lo (bf16 each); C += Ahi*Bhi + Ahi*Blo + Alo*Bhi.
// Block tile 128x128, BK=32, 256 threads (8 warps, 4x2 grid, warp tile 32x64).
// smem padded stride 40 bf16 (80B) -> conflict-free ldmatrix.

#define AST 40   // smem row stride in bf16 elements

__device__ __forceinline__ void ldmx4(uint32_t& r0, uint32_t& r1, uint32_t& r2,
                                      uint32_t& r3, uint32_t addr) {
    asm volatile("ldmatrix.sync.aligned.m8n8.x4.shared.b16 {%0,%1,%2,%3}, [%4];"
                 : "=r"(r0), "=r"(r1), "=r"(r2), "=r"(r3) : "r"(addr));
}
__device__ __forceinline__ void mma_bf16(float* c, const uint32_t* a, const uint32_t* b) {
    asm volatile(
        "mma.sync.aligned.m16n8k16.row.col.f32.bf16.bf16.f32 "
        "{%0,%1,%2,%3}, {%4,%5,%6,%7}, {%8,%9}, {%0,%1,%2,%3};"
        : "+f"(c[0]), "+f"(c[1]), "+f"(c[2]), "+f"(c[3])
        : "r"(a[0]), "r"(a[1]), "r"(a[2]), "r"(a[3]), "r"(b[0]), "r"(b[1]));
}
__device__ __forceinline__ uint32_t smem_u32(const void* p) {
    uint32_t a;
    asm("{ .reg .u64 t; cvta.to.shared.u64 t, %1; cvt.u32.u64 %0, t; }" : "=r"(a) : "l"(p));
    return a;
}
// split float4 into packed bf16x2 hi / lo
__device__ __forceinline__ void split4(float4 v, uint2& hi, uint2& lo) {
    __nv_bfloat16 hx = __float2bfloat16(v.x), hy = __float2bfloat16(v.y);
    __nv_bfloat16 hz = __float2bfloat16(v.z), hw = __float2bfloat16(v.w);
    __nv_bfloat16 lx = __float2bfloat16(v.x - __bfloat162float(hx));
    __nv_bfloat16 ly = __float2bfloat16(v.y - __bfloat162float(hy));
    __nv_bfloat16 lz = __float2bfloat16(v.z - __bfloat162float(hz));
    __nv_bfloat16 lw = __float2bfloat16(v.w - __bfloat162float(hw));
    __nv_bfloat162 h01 = __halves2bfloat162(hx, hy), h23 = __halves2bfloat162(hz, hw);
    __nv_bfloat162 l01 = __halves2bfloat162(lx, ly), l23 = __halves2bfloat162(lz, lw);
    hi.x = *(uint32_t*)&h01; hi.y = *(uint32_t*)&h23;
    lo.x = *(uint32_t*)&l01; lo.y = *(uint32_t*)&l23;
}

__global__ void __launch_bounds__(256, 1) mma_gemm_kernel(
    const float* __restrict__ A, int lda,
    const float* __restrict__ W,
    float* __restrict__ C, int ldc,
    int M, int bsA, int bsW, int bsC) {
    A += (size_t)blockIdx.z * bsA;
    W += (size_t)blockIdx.z * bsW;
    C += (size_t)blockIdx.z * bsC;

    __shared__ __nv_bfloat16 sAhi[128 * AST];
    __shared__ __nv_bfloat16 sAlo[128 * AST];
    __shared__ __nv_bfloat16 sBhi[128 * AST];
    __shared__ __nv_bfloat16 sBlo[128 * AST];

    int tid = threadIdx.x;
    int lane = tid & 31, wid = tid >> 5;
    int m0 = blockIdx.x * 128;
    int n0 = blockIdx.y * 128;
    int wm = (wid & 3) * 32;       // warp M offset
    int wn = (wid >> 2) * 64;      // warp N offset

    // loader mapping: idx -> (row, c4): 8 float4 per 128-row, 1024 total, 4/thread
    int lrow[4], lc4[4];
#pragma unroll
    for (int it = 0; it < 4; it++) {
        int idx = tid + it * 256;
        lrow[it] = idx >> 3;
        lc4[it]  = (idx & 7) << 2;
    }

    float acc[2][8][4];
#pragma unroll
    for (int i = 0; i < 2; i++)
#pragma unroll
        for (int j = 0; j < 8; j++)
#pragma unroll
            for (int k = 0; k < 4; k++) acc[i][j][k] = 0.f;

    uint32_t baseAhi = smem_u32(sAhi), baseAlo = smem_u32(sAlo);
    uint32_t baseBhi = smem_u32(sBhi), baseBlo = smem_u32(sBlo);

    // ldmatrix lane addressing (element offsets within tile, x2 for bytes)
    // A (m16k16 x4): row = base_m + (lane&15), k_elem = (lane>>4)*8
    int a_r = lane & 15, a_k = (lane >> 4) << 3;
    // B (two n8k16 tiles per x4): mat = lane>>3; n = (mat>>1)*8 + (lane&7); k = (mat&1)*8
    int b_mat = lane >> 3;
    int b_n = ((b_mat >> 1) << 3) + (lane & 7);
    int b_k = (b_mat & 1) << 3;

    for (int k0 = 0; k0 < 1024; k0 += 32) {
        // ---- load + split chunk ----
#pragma unroll
        for (int it = 0; it < 4; it++) {
            int row = lrow[it], c4 = lc4[it];
            int off = row * AST + c4;
            int am = m0 + row;
            float4 av = (am < M) ? *(const float4*)(A + (size_t)am * lda + k0 + c4)
                                 : make_float4(0.f, 0.f, 0.f, 0.f);
            uint2 hi, lo;
            split4(av, hi, lo);
            *(uint2*)(sAhi + off) = hi;
            *(uint2*)(sAlo + off) = lo;
            float4 wv = *(const float4*)(W + (size_t)(n0 + row) * 1024 + k0 + c4);
            split4(wv, hi, lo);
            *(uint2*)(sBhi + off) = hi;
            *(uint2*)(sBlo + off) = lo;
        }
        __syncthreads();
        // ---- compute 2 k16 steps ----
#pragma unroll
        for (int ks = 0; ks < 2; ks++) {
            int kbase = ks * 16;
            uint32_t ahi[2][4], alo[2][4];
#pragma unroll
            for (int mt = 0; mt < 2; mt++) {
                uint32_t aoff = (uint32_t)((wm + mt * 16 + a_r) * AST + kbase + a_k) * 2;
                ldmx4(ahi[mt][0], ahi[mt][1], ahi[mt][2], ahi[mt][3], baseAhi + aoff);
                ldmx4(alo[mt][0], alo[mt][1], alo[mt][2], alo[mt][3], baseAlo + aoff);
            }
            uint32_t bhi[8][2], blo[8][2];
#pragma unroll
            for (int np = 0; np < 4; np++) {
                uint32_t boff = (uint32_t)((wn + np * 16 + b_n) * AST + kbase + b_k) * 2;
                uint32_t r0, r1, r2, r3;
                ldmx4(r0, r1, r2, r3, baseBhi + boff);
                bhi[np * 2][0] = r0; bhi[np * 2][1] = r1;
                bhi[np * 2 + 1][0] = r2; bhi[np * 2 + 1][1] = r3;
                ldmx4(r0, r1, r2, r3, baseBlo + boff);
                blo[np * 2][0] = r0; blo[np * 2][1] = r1;
                blo[np * 2 + 1][0] = r2; blo[np * 2 + 1][1] = r3;
            }
#pragma unroll
            for (int mt = 0; mt < 2; mt++)
#pragma unroll
                for (int nt = 0; nt < 8; nt++) {
                    mma_bf16(acc[mt][nt], ahi[mt], bhi[nt]);
                    mma_bf16(acc[mt][nt], ahi[mt], blo[nt]);
                    mma_bf16(acc[mt][nt], alo[mt], bhi[nt]);
                }
        }
        __syncthreads();
    }

    // ---- epilogue ----
    int crow0 = m0 + wm + (lane >> 2);
    int ccol0 = n0 + wn + ((lane & 3) << 1);
#pragma unroll
    for (int mt = 0; mt < 2; mt++) {
#pragma unroll
        for (int nt = 0; nt < 8; nt++) {
            int m1 = crow0 + mt * 16;
            int m2 = m1 + 8;
            int n = ccol0 + nt * 8;
            if (m1 < M)
                *(float2*)(C + (size_t)m1 * ldc + n) = make_float2(acc[mt][nt][0], acc[mt][nt][1]);
            if (m2 < M)
                *(float2*)(C + (size_t)m2 * ldc + n) = make_float2(acc[mt][nt][2], acc[mt][nt][3]);
        }
    }
}

// ---------------- launch -------------------------------------------------------
extern "C" void kernel_launch(void* const* d_in, const int* in_sizes, int n_in,
                              void* d_out, int out_size) {
    const float* hidden     = (const float*)d_in[0];
    const float* boundaries = (const float*)d_in[1];
    const float* lengths    = (const float*)d_in[2];
    const float* lquery     = (const float*)d_in[3];
    const float* Wk         = (const float*)d_in[4];
    const float* Wv         = (const float*)d_in[5];
    const float* Wo         = (const float*)d_in[6];
    const float* gamma      = (const float*)d_in[7];
    const float* beta       = (const float*)d_in[8];
    float* out = (float*)d_out;

    float *p_pooledH, *p_pooled;
    cudaGetSymbolAddress((void**)&p_pooledH, g_pooledH);
    cudaGetSymbolAddress((void**)&p_pooled,  g_pooled);

    seg_kernel<<<B, 256>>>(boundaries, lengths);
    qk_kernel<<<(H * D + 255) / 256, 256>>>(lquery, Wk);
    ln_scores_kernel<<<B * L, 256>>>(hidden, gamma, beta);
    softmax_kernel<<<B * S, 256>>>();
    pool_kernel<<<B * S, 256>>>();

    // step 6: pooled[bs, h*128+n] = sum_k pooledH[bs,h,k] * Wv[h*128+n, k]
    {
        dim3 grid((B * S + 127) / 128, 1, H);
        mma_gemm_kernel<<<grid, 256>>>(p_pooledH, H * D, Wv, p_pooled, D,
                                       B * S, D, HD * 1024, HD);
    }
    // step 7: out[bs, n] = sum_k pooled[bs,k] * Wo[n,k]
    {
        dim3 grid((B * S + 127) / 128, D / 128, 1);
        mma_gemm_kernel<<<grid, 256>>>(p_pooled, D, Wo, out, D,
                                       B * S, 0, 0, 0);
    }
}

// round 7
// speedup vs baseline: 1.8421x; 1.0891x over previous
#include <cuda_runtime.h>
#include <cuda_bf16.h>
#include <math.h>
#include <stdint.h>

// Problem constants
#define B 8
#define L 1500
#define D 1024
#define H 8
#define HD 128
#define S 300
#define SCALE 0.08838834764831845f   // 1/sqrt(128)
#define EPS 1e-5f

// ---------------- scratch (device globals; no allocation allowed) -------------
__device__ float g_hn[B * L * D];            // 49.2 MB  normalized hidden
__device__ float g_scores[B * H * L];
__device__ float g_w[B * H * L];
__device__ float g_qk[H * D];
__device__ int   g_seg_start[B * S];
__device__ int   g_seg_cnt[B * S];
// bf16 split operand buffers
__device__ __align__(16) __nv_bfloat16 g_pHhi[B * S * H * D];   // 39.3 MB
__device__ __align__(16) __nv_bfloat16 g_pHlo[B * S * H * D];   // 39.3 MB
__device__ __align__(16) __nv_bfloat16 g_phi[B * S * D];        // 4.9 MB
__device__ __align__(16) __nv_bfloat16 g_plo[B * S * D];        // 4.9 MB
__device__ __align__(16) __nv_bfloat16 g_Wvhi[D * D];
__device__ __align__(16) __nv_bfloat16 g_Wvlo[D * D];
__device__ __align__(16) __nv_bfloat16 g_Wohi[D * D];
__device__ __align__(16) __nv_bfloat16 g_Wolo[D * D];

// ---------------- warp helpers -------------------------------------------------
__device__ __forceinline__ float warp_sum(float v) {
#pragma unroll
    for (int o = 16; o > 0; o >>= 1) v += __shfl_xor_sync(0xffffffffu, v, o);
    return v;
}
__device__ __forceinline__ float warp_max(float v) {
#pragma unroll
    for (int o = 16; o > 0; o >>= 1) v = fmaxf(v, __shfl_xor_sync(0xffffffffu, v, o));
    return v;
}
__device__ __forceinline__ uint32_t smem_u32(const void* p) {
    uint32_t a;
    asm("{ .reg .u64 t; cvta.to.shared.u64 t, %1; cvt.u32.u64 %0, t; }" : "=r"(a) : "l"(p));
    return a;
}
// split float4 into packed bf16x2 hi / lo
__device__ __forceinline__ void split4(float4 v, uint2& hi, uint2& lo) {
    __nv_bfloat16 hx = __float2bfloat16(v.x), hy = __float2bfloat16(v.y);
    __nv_bfloat16 hz = __float2bfloat16(v.z), hw = __float2bfloat16(v.w);
    __nv_bfloat16 lx = __float2bfloat16(v.x - __bfloat162float(hx));
    __nv_bfloat16 ly = __float2bfloat16(v.y - __bfloat162float(hy));
    __nv_bfloat16 lz = __float2bfloat16(v.z - __bfloat162float(hz));
    __nv_bfloat16 lw = __float2bfloat16(v.w - __bfloat162float(hw));
    __nv_bfloat162 h01 = __halves2bfloat162(hx, hy), h23 = __halves2bfloat162(hz, hw);
    __nv_bfloat162 l01 = __halves2bfloat162(lx, ly), l23 = __halves2bfloat162(lz, lw);
    hi.x = *(uint32_t*)&h01; hi.y = *(uint32_t*)&h23;
    lo.x = *(uint32_t*)&l01; lo.y = *(uint32_t*)&l23;
}
__device__ __forceinline__ void split2(float a, float b, uint32_t& hi, uint32_t& lo) {
    __nv_bfloat16 ha = __float2bfloat16(a), hb = __float2bfloat16(b);
    __nv_bfloat16 la = __float2bfloat16(a - __bfloat162float(ha));
    __nv_bfloat16 lb = __float2bfloat16(b - __bfloat162float(hb));
    __nv_bfloat162 hp = __halves2bfloat162(ha, hb), lp = __halves2bfloat162(la, lb);
    hi = *(uint32_t*)&hp; lo = *(uint32_t*)&lp;
}

// ---------------- mma helpers ---------------------------------------------------
__device__ __forceinline__ void ldmx4(uint32_t& r0, uint32_t& r1, uint32_t& r2,
                                      uint32_t& r3, uint32_t addr) {
    asm volatile("ldmatrix.sync.aligned.m8n8.x4.shared.b16 {%0,%1,%2,%3}, [%4];"
                 : "=r"(r0), "=r"(r1), "=r"(r2), "=r"(r3) : "r"(addr));
}
__device__ __forceinline__ void mma_bf16(float* c, const uint32_t* a, const uint32_t* b) {
    asm volatile(
        "mma.sync.aligned.m16n8k16.row.col.f32.bf16.bf16.f32 "
        "{%0,%1,%2,%3}, {%4,%5,%6,%7}, {%8,%9}, {%0,%1,%2,%3};"
        : "+f"(c[0]), "+f"(c[1]), "+f"(c[2]), "+f"(c[3])
        : "r"(a[0]), "r"(a[1]), "r"(a[2]), "r"(a[3]), "r"(b[0]), "r"(b[1]));
}
__device__ __forceinline__ void cpa16(uint32_t dst, const void* src, bool valid) {
    int sz = valid ? 16 : 0;
    asm volatile("cp.async.ca.shared.global [%0], [%1], 16, %2;"
                 :: "r"(dst), "l"(src), "r"(sz) : "memory");
}
#define CP_COMMIT() asm volatile("cp.async.commit_group;" ::: "memory")
#define CP_WAIT(n)  asm volatile("cp.async.wait_group %0;" :: "n"(n) : "memory")

// ---------------- 1) segment ranges -------------------------------------------
__global__ void seg_kernel(const float* __restrict__ boundaries,
                           const float* __restrict__ lengths) {
    __shared__ float sb[L];
    __shared__ int scnt[S];
    __shared__ int sstart[S];
    int b = blockIdx.x;
    for (int i = threadIdx.x; i < L; i += blockDim.x) sb[i] = boundaries[b * L + i];
    for (int i = threadIdx.x; i < S; i += blockDim.x) { scnt[i] = 0; sstart[i] = 0; }
    __syncthreads();
    if (threadIdx.x == 0) {
        int alen = (int)(lengths[b] * (float)L);
        int cum = 0;
        for (int t = 0; t < L; t++) {
            int bd = sb[t] > 0.5f ? 1 : 0;
            cum += bd;
            int sid = cum - bd;
            if (t < alen && sid < S) {
                if (scnt[sid] == 0) sstart[sid] = t;
                scnt[sid]++;
            }
        }
    }
    __syncthreads();
    for (int i = threadIdx.x; i < S; i += blockDim.x) {
        g_seg_cnt[b * S + i]   = scnt[i];
        g_seg_start[b * S + i] = sstart[i];
    }
}

// ---------------- 2) qk[h,j] = sum_hd q[h*HD+hd] * Wk[h*HD+hd, j] --------------
__global__ void qk_kernel(const float* __restrict__ q, const float* __restrict__ Wk) {
    int idx = blockIdx.x * blockDim.x + threadIdx.x;   // h*D + j
    if (idx >= H * D) return;
    int h = idx >> 10, j = idx & (D - 1);
    float acc = 0.f;
#pragma unroll 8
    for (int hd = 0; hd < HD; hd++)
        acc += q[h * HD + hd] * Wk[(h * HD + hd) * D + j];
    g_qk[idx] = acc;
}

// ---------------- 2b) weight split: fp32 -> bf16 hi/lo -------------------------
__global__ void __launch_bounds__(256) wsplit_kernel(
    const float* __restrict__ Wsrc, __nv_bfloat16* __restrict__ hi,
    __nv_bfloat16* __restrict__ lo) {
    int i = blockIdx.x * blockDim.x + threadIdx.x;   // float4 index, 262144 total
    float4 v = ((const float4*)Wsrc)[i];
    uint2 h, l;
    split4(v, h, l);
    ((uint2*)hi)[i] = h;
    ((uint2*)lo)[i] = l;
}

// ---------------- 3) LayerNorm + scores fused ----------------------------------
__global__ void __launch_bounds__(256) ln_scores_kernel(
    const float* __restrict__ hidden, const float* __restrict__ gamma,
    const float* __restrict__ beta) {
    int tok = blockIdx.x;            // b*L + t
    int b = tok / L, t = tok - b * L;
    int tid = threadIdx.x;
    int lane = tid & 31, wid = tid >> 5;

    float4 x = ((const float4*)(hidden + (size_t)tok * D))[tid];
    float s  = x.x + x.y + x.z + x.w;
    float ss = x.x * x.x + x.y * x.y + x.z * x.z + x.w * x.w;

    __shared__ float sred[2][8];
    float ws  = warp_sum(s);
    float wss = warp_sum(ss);
    if (lane == 0) { sred[0][wid] = ws; sred[1][wid] = wss; }
    __syncthreads();
    __shared__ float stats[2];
    if (tid == 0) {
        float a = 0.f, b2 = 0.f;
#pragma unroll
        for (int i = 0; i < 8; i++) { a += sred[0][i]; b2 += sred[1][i]; }
        float mean = a * (1.f / (float)D);
        float var  = b2 * (1.f / (float)D) - mean * mean;
        stats[0] = mean;
        stats[1] = rsqrtf(var + EPS);
    }
    __syncthreads();
    float mean = stats[0], rstd = stats[1];

    float4 g  = ((const float4*)gamma)[tid];
    float4 be = ((const float4*)beta)[tid];
    float4 hv;
    hv.x = (x.x - mean) * rstd * g.x + be.x;
    hv.y = (x.y - mean) * rstd * g.y + be.y;
    hv.z = (x.z - mean) * rstd * g.z + be.z;
    hv.w = (x.w - mean) * rstd * g.w + be.w;
    ((float4*)(g_hn + (size_t)tok * D))[tid] = hv;

    float p[H];
#pragma unroll
    for (int h = 0; h < H; h++) {
        float4 qv = ((const float4*)g_qk)[h * (D / 4) + tid];
        p[h] = hv.x * qv.x + hv.y * qv.y + hv.z * qv.z + hv.w * qv.w;
    }
    __shared__ float pred[H][8];
#pragma unroll
    for (int h = 0; h < H; h++) {
        float ph = warp_sum(p[h]);
        if (lane == 0) pred[h][wid] = ph;
    }
    __syncthreads();
    if (tid < H) {
        float v = 0.f;
#pragma unroll
        for (int w = 0; w < 8; w++) v += pred[tid][w];
        g_scores[((size_t)b * H + tid) * L + t] = v * SCALE;
    }
}

// ---------------- 4) segment softmax -------------------------------------------
__global__ void softmax_kernel() {
    int bs = blockIdx.x;
    int b = bs / S;
    int st = g_seg_start[bs], cnt = g_seg_cnt[bs];
    if (cnt == 0) return;
    int lane = threadIdx.x & 31, h = threadIdx.x >> 5;
    const float* srow = g_scores + ((size_t)b * H + h) * L + st;
    float mx = -1e30f;
    for (int i = lane; i < cnt; i += 32) mx = fmaxf(mx, srow[i]);
    mx = warp_max(mx);
    float sum = 0.f;
    for (int i = lane; i < cnt; i += 32) sum += expf(srow[i] - mx);
    sum = warp_sum(sum);
    float inv = 1.f / sum;
    float* wrow = g_w + ((size_t)b * H + h) * L + st;
    for (int i = lane; i < cnt; i += 32) wrow[i] = expf(srow[i] - mx) * inv;
}

// ---------------- 5) sparse pooling -> bf16 hi/lo output -----------------------
__global__ void __launch_bounds__(256) pool_kernel() {
    int bs = blockIdx.x;
    int b = bs / S;
    int tid = threadIdx.x;
    int st = g_seg_start[bs], cnt = g_seg_cnt[bs];
    float4 acc[H];
#pragma unroll
    for (int h = 0; h < H; h++) acc[h] = make_float4(0.f, 0.f, 0.f, 0.f);
    for (int i = 0; i < cnt; i++) {
        int t = st + i;
        float4 x = ((const float4*)(g_hn + ((size_t)(b * L + t)) * D))[tid];
        float wh[H];
#pragma unroll
        for (int h = 0; h < H; h++) wh[h] = g_w[((size_t)b * H + h) * L + t];
#pragma unroll
        for (int h = 0; h < H; h++) {
            acc[h].x += wh[h] * x.x;
            acc[h].y += wh[h] * x.y;
            acc[h].z += wh[h] * x.z;
            acc[h].w += wh[h] * x.w;
        }
    }
#pragma unroll
    for (int h = 0; h < H; h++) {
        uint2 hi, lo;
        split4(acc[h], hi, lo);
        size_t base = ((size_t)bs * H + h) * D + tid * 4;
        *(uint2*)(g_pHhi + base) = hi;
        *(uint2*)(g_pHlo + base) = lo;
    }
}

// ---------------- 6/7) pipelined bf16 split GEMM -------------------------------
// C[m,n] = sum_k A[m,k]*W[n,k]; operands pre-split bf16 hi/lo in global.
// Block tile 128x128, BK=32, 256 threads, 2-stage cp.async pipeline.
// smem: 2 stages x 4 tiles x 128 rows x 80B (AST=40 bf16, conflict-free ldmatrix).
#define AST 40
#define TILE_B (128 * AST * 2)     // 10240 bytes per tile
#define STAGE_B (4 * TILE_B)       // 40960 bytes per stage
#define GEMM_SMEM (2 * STAGE_B)    // 81920 bytes

__global__ void __launch_bounds__(256, 1) mma_gemm_kernel(
    const __nv_bfloat16* __restrict__ Ahi, const __nv_bfloat16* __restrict__ Alo,
    int lda,
    const __nv_bfloat16* __restrict__ Bhi, const __nv_bfloat16* __restrict__ Blo,
    float* __restrict__ C, __nv_bfloat16* __restrict__ Chi,
    __nv_bfloat16* __restrict__ Clo, int ldc,
    int M, int bsA, int bsB, int bsC) {
    extern __shared__ char smem[];
    int z = blockIdx.z;
    Ahi += (size_t)z * bsA; Alo += (size_t)z * bsA;
    Bhi += (size_t)z * bsB; Blo += (size_t)z * bsB;
    if (C)   C   += (size_t)z * bsC;
    if (Chi) { Chi += (size_t)z * bsC; Clo += (size_t)z * bsC; }

    uint32_t smem_base = smem_u32(smem);
    int tid = threadIdx.x;
    int lane = tid & 31, wid = tid >> 5;
    int m0 = blockIdx.x * 128;
    int n0 = blockIdx.y * 128;
    int wm = (wid & 3) * 32;
    int wn = (wid >> 2) * 64;

    // loader mapping: thread handles rows (tid>>2) and (tid>>2)+64, 16B chunk tid&3
    int lrow = tid >> 2;
    int lch  = tid & 3;

    float acc[2][8][4];
#pragma unroll
    for (int i = 0; i < 2; i++)
#pragma unroll
        for (int j = 0; j < 8; j++)
#pragma unroll
            for (int k = 0; k < 4; k++) acc[i][j][k] = 0.f;

    // ldmatrix lane addressing
    int a_r = lane & 15, a_k = (lane >> 4) << 3;
    int b_mat = lane >> 3;
    int b_n = ((b_mat >> 1) << 3) + (lane & 7);
    int b_k = (b_mat & 1) << 3;

    auto issue_chunk = [&](int ch, int stage) {
        int k0 = ch * 32;
        uint32_t sb = smem_base + stage * STAGE_B;
#pragma unroll
        for (int half = 0; half < 2; half++) {
            int row = lrow + half * 64;
            uint32_t doff = (uint32_t)(row * 80 + lch * 16);
            int am = m0 + row;
            bool av = am < M;
            int amc = av ? am : (M - 1);
            size_t aoff = (size_t)amc * lda + k0 + lch * 8;
            cpa16(sb + 0 * TILE_B + doff, Ahi + aoff, av);
            cpa16(sb + 1 * TILE_B + doff, Alo + aoff, av);
            size_t boff = (size_t)(n0 + row) * 1024 + k0 + lch * 8;
            cpa16(sb + 2 * TILE_B + doff, Bhi + boff, true);
            cpa16(sb + 3 * TILE_B + doff, Blo + boff, true);
        }
        CP_COMMIT();
    };

    issue_chunk(0, 0);

    for (int ch = 0; ch < 32; ch++) {
        if (ch + 1 < 32) {
            issue_chunk(ch + 1, (ch + 1) & 1);
            CP_WAIT(1);
        } else {
            CP_WAIT(0);
        }
        __syncthreads();
        uint32_t sb = smem_base + (ch & 1) * STAGE_B;
        uint32_t baseAhi = sb, baseAlo = sb + TILE_B;
        uint32_t baseBhi = sb + 2 * TILE_B, baseBlo = sb + 3 * TILE_B;
#pragma unroll
        for (int ks = 0; ks < 2; ks++) {
            int kbase = ks * 16;
            uint32_t ahi[2][4], alo[2][4];
#pragma unroll
            for (int mt = 0; mt < 2; mt++) {
                uint32_t aoff = (uint32_t)((wm + mt * 16 + a_r) * AST + kbase + a_k) * 2;
                ldmx4(ahi[mt][0], ahi[mt][1], ahi[mt][2], ahi[mt][3], baseAhi + aoff);
                ldmx4(alo[mt][0], alo[mt][1], alo[mt][2], alo[mt][3], baseAlo + aoff);
            }
            uint32_t bhi[8][2], blo[8][2];
#pragma unroll
            for (int np = 0; np < 4; np++) {
                uint32_t boff = (uint32_t)((wn + np * 16 + b_n) * AST + kbase + b_k) * 2;
                uint32_t r0, r1, r2, r3;
                ldmx4(r0, r1, r2, r3, baseBhi + boff);
                bhi[np * 2][0] = r0; bhi[np * 2][1] = r1;
                bhi[np * 2 + 1][0] = r2; bhi[np * 2 + 1][1] = r3;
                ldmx4(r0, r1, r2, r3, baseBlo + boff);
                blo[np * 2][0] = r0; blo[np * 2][1] = r1;
                blo[np * 2 + 1][0] = r2; blo[np * 2 + 1][1] = r3;
            }
#pragma unroll
            for (int mt = 0; mt < 2; mt++)
#pragma unroll
                for (int nt = 0; nt < 8; nt++) {
                    mma_bf16(acc[mt][nt], ahi[mt], bhi[nt]);
                    mma_bf16(acc[mt][nt], ahi[mt], blo[nt]);
                    mma_bf16(acc[mt][nt], alo[mt], bhi[nt]);
                }
        }
        __syncthreads();
    }

    // ---- epilogue ----
    int crow0 = m0 + wm + (lane >> 2);
    int ccol0 = n0 + wn + ((lane & 3) << 1);
#pragma unroll
    for (int mt = 0; mt < 2; mt++) {
#pragma unroll
        for (int nt = 0; nt < 8; nt++) {
            int m1 = crow0 + mt * 16;
            int m2 = m1 + 8;
            int n = ccol0 + nt * 8;
            if (Chi) {
                if (m1 < M) {
                    uint32_t hi, lo;
                    split2(acc[mt][nt][0], acc[mt][nt][1], hi, lo);
                    *(uint32_t*)(Chi + (size_t)m1 * ldc + n) = hi;
                    *(uint32_t*)(Clo + (size_t)m1 * ldc + n) = lo;
                }
                if (m2 < M) {
                    uint32_t hi, lo;
                    split2(acc[mt][nt][2], acc[mt][nt][3], hi, lo);
                    *(uint32_t*)(Chi + (size_t)m2 * ldc + n) = hi;
                    *(uint32_t*)(Clo + (size_t)m2 * ldc + n) = lo;
                }
            } else {
                if (m1 < M)
                    *(float2*)(C + (size_t)m1 * ldc + n) =
                        make_float2(acc[mt][nt][0], acc[mt][nt][1]);
                if (m2 < M)
                    *(float2*)(C + (size_t)m2 * ldc + n) =
                        make_float2(acc[mt][nt][2], acc[mt][nt][3]);
            }
        }
    }
}

// ---------------- launch -------------------------------------------------------
extern "C" void kernel_launch(void* const* d_in, const int* in_sizes, int n_in,
                              void* d_out, int out_size) {
    const float* hidden     = (const float*)d_in[0];
    const float* boundaries = (const float*)d_in[1];
    const float* lengths    = (const float*)d_in[2];
    const float* lquery     = (const float*)d_in[3];
    const float* Wk         = (const float*)d_in[4];
    const float* Wv         = (const float*)d_in[5];
    const float* Wo         = (const float*)d_in[6];
    const float* gamma      = (const float*)d_in[7];
    const float* beta       = (const float*)d_in[8];
    float* out = (float*)d_out;

    __nv_bfloat16 *p_pHhi, *p_pHlo, *p_phi, *p_plo;
    __nv_bfloat16 *p_Wvhi, *p_Wvlo, *p_Wohi, *p_Wolo;
    cudaGetSymbolAddress((void**)&p_pHhi, g_pHhi);
    cudaGetSymbolAddress((void**)&p_pHlo, g_pHlo);
    cudaGetSymbolAddress((void**)&p_phi,  g_phi);
    cudaGetSymbolAddress((void**)&p_plo,  g_plo);
    cudaGetSymbolAddress((void**)&p_Wvhi, g_Wvhi);
    cudaGetSymbolAddress((void**)&p_Wvlo, g_Wvlo);
    cudaGetSymbolAddress((void**)&p_Wohi, g_Wohi);
    cudaGetSymbolAddress((void**)&p_Wolo, g_Wolo);

    static bool attr_set = false;
    if (!attr_set) {
        cudaFuncSetAttribute(mma_gemm_kernel,
                             cudaFuncAttributeMaxDynamicSharedMemorySize, GEMM_SMEM);
        attr_set = true;
    }

    seg_kernel<<<B, 256>>>(boundaries, lengths);
    qk_kernel<<<(H * D + 255) / 256, 256>>>(lquery, Wk);
    wsplit_kernel<<<D * D / 4 / 256, 256>>>(Wv, p_Wvhi, p_Wvlo);
    wsplit_kernel<<<D * D / 4 / 256, 256>>>(Wo, p_Wohi, p_Wolo);
    ln_scores_kernel<<<B * L, 256>>>(hidden, gamma, beta);
    softmax_kernel<<<B * S, 256>>>();
    pool_kernel<<<B * S, 256>>>();

    // step 6: pooled[bs, h*128+n] = sum_k pooledH[bs,h,k] * Wv[h*128+n, k]
    {
        dim3 grid((B * S + 127) / 128, 1, H);
        mma_gemm_kernel<<<grid, 256, GEMM_SMEM>>>(
            p_pHhi, p_pHlo, H * D, p_Wvhi, p_Wvlo,
            nullptr, p_phi, p_plo, D,
            B * S, D, HD * 1024, HD);
    }
    // step 7: out[bs, n] = sum_k pooled[bs,k] * Wo[n,k]
    {
        dim3 grid((B * S + 127) / 128, D / 128, 1);
        mma_gemm_kernel<<<grid, 256, GEMM_SMEM>>>(
            p_phi, p_plo, D, p_Wohi, p_Wolo,
            out, nullptr, nullptr, D,
            B * S, 0, 0, 0);
    }
}